// round 1
// baseline (speedup 1.0000x reference)
#include <cuda_runtime.h>
#include <cstdint>

// Problem dims
#define B_  4096
#define D_  4624
#define L_  68
#define E_  1024

// GEMM tiling
#define BM 128
#define BN 128
#define BK 32
#define KPAD 36          // smem row stride (u32) -> conflict-free frag loads
#define THREADS 256

// Scratch (static device allocations are allowed; cudaMalloc is not)
__device__ float g_h[(size_t)B_ * 2 * E_];    // [4096 x 2048] = relu(x@fc11^T)|relu(x@fc12^T)
__device__ float g_h51[(size_t)B_ * L_];      // decoder branch-0 output

__device__ __forceinline__ uint32_t f2tf32(float x) {
    uint32_t r;
    asm("cvt.rna.tf32.f32 %0, %1;" : "=r"(r) : "f"(x));
    return r;
}

__device__ __forceinline__ void mma_tf32(float* c, uint32_t a0, uint32_t a1,
                                         uint32_t a2, uint32_t a3,
                                         uint32_t b0, uint32_t b1) {
    asm volatile(
        "mma.sync.aligned.m16n8k8.row.col.f32.tf32.tf32.f32 "
        "{%0,%1,%2,%3}, {%4,%5,%6,%7}, {%8,%9}, {%0,%1,%2,%3};\n"
        : "+f"(c[0]), "+f"(c[1]), "+f"(c[2]), "+f"(c[3])
        : "r"(a0), "r"(a1), "r"(a2), "r"(a3), "r"(b0), "r"(b1));
}

// MODE 0: C = relu(A @ W^T + b), dual weight select by n0 (encoder fc11/fc12)
// MODE 1: C = A @ W^T + b, batched over blockIdx.z (mu / logvar heads)
// MODE 2: C = sigmoid(outer(h51) @ W^T + b); A synthesized from h51 (recon)
template <int MODE>
__global__ void __launch_bounds__(THREADS, 1)
gemm_tf32(const float* __restrict__ A, int lda,
          const float* __restrict__ W0, const float* __restrict__ W1,
          const float* __restrict__ bias0, const float* __restrict__ bias1,
          const float* __restrict__ h51,
          float* __restrict__ C, int ldc,
          int M, int N, int K, int nsplit, int batchStrideC)
{
    extern __shared__ unsigned char smem_raw[];
    uint32_t* As   = reinterpret_cast<uint32_t*>(smem_raw);          // 2*BM*KPAD
    uint32_t* Bs   = As + 2 * BM * KPAD;                             // 2*BN*KPAD
    float*    h51s = reinterpret_cast<float*>(Bs + 2 * BN * KPAD);   // BM*68 (MODE 2)

    const int tid = threadIdx.x;
    const int m0  = blockIdx.y * BM;
    const int n0  = blockIdx.x * BN;

    const float* W;
    const float* bias;
    int wn0;
    int Nw;
    if (MODE == 0) {
        if (n0 >= nsplit) { W = W1; bias = bias1; wn0 = n0 - nsplit; }
        else              { W = W0; bias = bias0; wn0 = n0; }
        Nw = nsplit;
    } else if (MODE == 1) {
        int z = blockIdx.z;
        A += (size_t)z * nsplit;                 // nsplit = column offset into g_h
        W    = z ? W1 : W0;
        bias = z ? bias1 : bias0;
        C   += (size_t)z * batchStrideC;
        wn0 = n0; Nw = N;
    } else {
        W = W0; bias = bias0; wn0 = n0; Nw = N;
    }

    if (MODE == 2) {
        // Stage h51 rows for this M-block once; A tiles are outer products of these.
        for (int idx = tid; idx < BM * L_; idx += THREADS) {
            int r = idx / L_, c = idx - r * L_;
            h51s[r * L_ + c] = h51[(size_t)(m0 + r) * L_ + c];
        }
        __syncthreads();
    }

    const int lrow = tid >> 3;          // 0..31
    const int lcol = (tid & 7) * 4;     // 0,4,...,28

    float4 aR[4], bR[4];

    auto loadAB = [&](int k0) {
#pragma unroll
        for (int i = 0; i < 4; i++) {
            int r = lrow + 32 * i;
            // ---- A ----
            if (MODE == 2) {
                float v0 = 0.f, v1 = 0.f, v2 = 0.f, v3 = 0.f;
                int kb = k0 + lcol;
                if (kb < K) {
                    const float* hr = h51s + r * L_;
                    int i0 = (kb + 0) / L_, j0 = (kb + 0) - i0 * L_;
                    int i1 = (kb + 1) / L_, j1 = (kb + 1) - i1 * L_;
                    int i2 = (kb + 2) / L_, j2 = (kb + 2) - i2 * L_;
                    int i3 = (kb + 3) / L_, j3 = (kb + 3) - i3 * L_;
                    v0 = hr[i0] * hr[j0];
                    v1 = hr[i1] * hr[j1];
                    v2 = hr[i2] * hr[j2];
                    v3 = hr[i3] * hr[j3];
                }
                aR[i] = make_float4(v0, v1, v2, v3);
            } else {
                if (k0 + lcol < K)
                    aR[i] = *reinterpret_cast<const float4*>(
                        A + (size_t)(m0 + r) * lda + k0 + lcol);
                else
                    aR[i] = make_float4(0.f, 0.f, 0.f, 0.f);
            }
            // ---- B (weights, [Nw, K] row-major; NT gemm) ----
            if ((wn0 + r < Nw) && (k0 + lcol < K))
                bR[i] = *reinterpret_cast<const float4*>(
                    W + (size_t)(wn0 + r) * K + k0 + lcol);
            else
                bR[i] = make_float4(0.f, 0.f, 0.f, 0.f);
        }
    };

    auto storeAB = [&](int buf) {
#pragma unroll
        for (int i = 0; i < 4; i++) {
            int r = lrow + 32 * i;
            uint4 av = make_uint4(f2tf32(aR[i].x), f2tf32(aR[i].y),
                                  f2tf32(aR[i].z), f2tf32(aR[i].w));
            uint4 bv = make_uint4(f2tf32(bR[i].x), f2tf32(bR[i].y),
                                  f2tf32(bR[i].z), f2tf32(bR[i].w));
            *reinterpret_cast<uint4*>(As + buf * BM * KPAD + r * KPAD + lcol) = av;
            *reinterpret_cast<uint4*>(Bs + buf * BN * KPAD + r * KPAD + lcol) = bv;
        }
    };

    float acc[2][8][4] = {};

    const int lane = tid & 31;
    const int warp = tid >> 5;
    const int wm = warp & 3;          // 4 warps along M
    const int wn = warp >> 2;         // 2 warps along N
    const int aBase = wm * 32 + (lane >> 2);
    const int bBase = wn * 64 + (lane >> 2);
    const int kq = lane & 3;

    auto compute = [&](int buf) {
        const uint32_t* Ab = As + buf * BM * KPAD;
        const uint32_t* Bb = Bs + buf * BN * KPAD;
#pragma unroll
        for (int kk = 0; kk < 4; kk++) {
            int k = kk * 8 + kq;
            uint32_t a[2][4];
#pragma unroll
            for (int mt = 0; mt < 2; mt++) {
                int r = aBase + mt * 16;
                a[mt][0] = Ab[r * KPAD + k];
                a[mt][1] = Ab[(r + 8) * KPAD + k];
                a[mt][2] = Ab[r * KPAD + k + 4];
                a[mt][3] = Ab[(r + 8) * KPAD + k + 4];
            }
#pragma unroll
            for (int nt = 0; nt < 8; nt++) {
                int c = bBase + nt * 8;
                uint32_t b0 = Bb[c * KPAD + k];
                uint32_t b1 = Bb[c * KPAD + k + 4];
#pragma unroll
                for (int mt = 0; mt < 2; mt++)
                    mma_tf32(acc[mt][nt], a[mt][0], a[mt][1], a[mt][2], a[mt][3],
                             b0, b1);
            }
        }
    };

    const int kt = (K + BK - 1) / BK;
    loadAB(0);
    storeAB(0);
    __syncthreads();
    for (int t = 0; t < kt; t++) {
        if (t + 1 < kt) loadAB((t + 1) * BK);
        compute(t & 1);
        if (t + 1 < kt) {
            __syncthreads();
            storeAB((t + 1) & 1);
            __syncthreads();
        }
    }

    // Epilogue: bias + activation + guarded store
#pragma unroll
    for (int mt = 0; mt < 2; mt++) {
        int row = m0 + wm * 32 + mt * 16 + (lane >> 2);
#pragma unroll
        for (int nt = 0; nt < 8; nt++) {
            int ncl = wn * 64 + nt * 8 + (lane & 3) * 2;
#pragma unroll
            for (int e = 0; e < 4; e++) {
                int r   = row + ((e >= 2) ? 8 : 0);
                int cl  = ncl + (e & 1);
                int col = n0 + cl;
                if (col < N) {
                    float v = acc[mt][nt][e] + bias[wn0 + cl];
                    if (MODE == 0) v = v > 0.f ? v : 0.f;
                    if (MODE == 2) v = 1.0f / (1.0f + __expf(-v));
                    C[(size_t)r * ldc + col] = v;
                }
            }
        }
    }
}

// z = mu + eps*exp(0.5*logvar); y = mu@fcy^T+b;
// h3_0 = z@W3[0]^T+b3[0] (no sigmoid for branch 0);
// h4_0 = sigmoid(h3_0@W4[0]^T+b4[0]); h51 = h4_0@W5[0]^T+b5[0].
// Branches 1..4 are dead code w.r.t. the outputs — skipped.
__global__ void __launch_bounds__(256, 1)
mid_kernel(const float* __restrict__ mu, const float* __restrict__ logvar,
           const float* __restrict__ eps,
           const float* __restrict__ W3, const float* __restrict__ b3,
           const float* __restrict__ W4, const float* __restrict__ b4,
           const float* __restrict__ W5, const float* __restrict__ b5,
           const float* __restrict__ fcy_w, const float* __restrict__ fcy_b,
           float* __restrict__ h51, float* __restrict__ y)
{
    extern __shared__ unsigned char smem_raw[];
    float* s   = reinterpret_cast<float*>(smem_raw);
    float* sW3 = s;                    // 68*69 (padded: conflict-free)
    float* sW4 = sW3 + L_ * 69;
    float* sW5 = sW4 + L_ * 69;
    float* sb3 = sW5 + L_ * 69;
    float* sb4 = sb3 + L_;
    float* sb5 = sb4 + L_;
    float* zs  = sb5 + L_;             // 8*68
    float* h3s = zs + 8 * L_;
    float* h4s = h3s + 8 * L_;

    const int tid = threadIdx.x;
    for (int idx = tid; idx < L_ * L_; idx += 256) {
        int o = idx / L_, d = idx - o * L_;
        sW3[o * 69 + d] = W3[idx];     // branch 0 = first 68*68
        sW4[o * 69 + d] = W4[idx];
        sW5[o * 69 + d] = W5[idx];     // idx map [0,...] -> W5[0]
    }
    for (int idx = tid; idx < L_; idx += 256) {
        sb3[idx] = b3[idx]; sb4[idx] = b4[idx]; sb5[idx] = b5[idx];
    }
    __syncthreads();

    const int lane = tid & 31, w = tid >> 5;
    const int row = blockIdx.x * 8 + w;
    const float* murow  = mu + (size_t)row * L_;
    const float* lvrow  = logvar + (size_t)row * L_;
    const float* epsrow = eps + (size_t)row * L_;
    float* zw  = zs + w * L_;
    float* h3w = h3s + w * L_;
    float* h4w = h4s + w * L_;

    float yp = 0.f;
    for (int o = lane; o < L_; o += 32) {
        float m_ = murow[o];
        zw[o] = m_ + epsrow[o] * expf(0.5f * lvrow[o]);
        yp += m_ * fcy_w[o];
    }
#pragma unroll
    for (int off = 16; off; off >>= 1) yp += __shfl_xor_sync(0xffffffffu, yp, off);
    if (lane == 0) y[row] = yp + fcy_b[0];
    __syncwarp();

    for (int o = lane; o < L_; o += 32) {
        float sacc = sb3[o];
        const float* wr = sW3 + o * 69;
#pragma unroll 4
        for (int d = 0; d < L_; d++) sacc += zw[d] * wr[d];
        h3w[o] = sacc;                 // branch 0: NO sigmoid
    }
    __syncwarp();
    for (int o = lane; o < L_; o += 32) {
        float sacc = sb4[o];
        const float* wr = sW4 + o * 69;
#pragma unroll 4
        for (int d = 0; d < L_; d++) sacc += h3w[d] * wr[d];
        h4w[o] = 1.0f / (1.0f + expf(-sacc));
    }
    __syncwarp();
    for (int o = lane; o < L_; o += 32) {
        float sacc = sb5[o];
        const float* wr = sW5 + o * 69;
#pragma unroll 4
        for (int d = 0; d < L_; d++) sacc += h4w[d] * wr[d];
        h51[(size_t)row * L_ + o] = sacc;
    }
}

extern "C" void kernel_launch(void* const* d_in, const int* in_sizes, int n_in,
                              void* d_out, int out_size)
{
    const float* x      = (const float*)d_in[0];
    const float* eps    = (const float*)d_in[1];
    const float* fc11_w = (const float*)d_in[2];
    const float* fc11_b = (const float*)d_in[3];
    const float* fc12_w = (const float*)d_in[4];
    const float* fc12_b = (const float*)d_in[5];
    const float* fc21_w = (const float*)d_in[6];
    const float* fc21_b = (const float*)d_in[7];
    const float* fc22_w = (const float*)d_in[8];
    const float* fc22_b = (const float*)d_in[9];
    const float* W3     = (const float*)d_in[10];
    const float* b3     = (const float*)d_in[11];
    const float* W4     = (const float*)d_in[12];
    const float* b4     = (const float*)d_in[13];
    const float* W5     = (const float*)d_in[14];
    const float* b5     = (const float*)d_in[15];
    const float* fc6_w  = (const float*)d_in[16];
    const float* fc6_b  = (const float*)d_in[17];
    const float* fcy_w  = (const float*)d_in[18];
    const float* fcy_b  = (const float*)d_in[19];

    float* out   = (float*)d_out;
    float* recon = out;                                  // [B, D]
    float* mu    = out + (size_t)B_ * D_;                // [B, L]
    float* lv    = mu + (size_t)B_ * L_;                 // [B, L]
    float* y     = lv + (size_t)B_ * L_;                 // [B, 1]

    float* hbuf; cudaGetSymbolAddress((void**)&hbuf, g_h);
    float* h51;  cudaGetSymbolAddress((void**)&h51, g_h51);

    const size_t smemG   = (size_t)(2 * BM * KPAD + 2 * BN * KPAD) * 4;   // 73728
    const size_t smemG2  = smemG + (size_t)BM * L_ * 4;                   // 108544
    const size_t smemMid = (size_t)(3 * L_ * 69 + 3 * L_ + 3 * 8 * L_) * 4;

    cudaFuncSetAttribute(gemm_tf32<0>, cudaFuncAttributeMaxDynamicSharedMemorySize, (int)smemG);
    cudaFuncSetAttribute(gemm_tf32<1>, cudaFuncAttributeMaxDynamicSharedMemorySize, (int)smemG);
    cudaFuncSetAttribute(gemm_tf32<2>, cudaFuncAttributeMaxDynamicSharedMemorySize, (int)smemG2);
    cudaFuncSetAttribute(mid_kernel,   cudaFuncAttributeMaxDynamicSharedMemorySize, (int)smemMid);

    // 1) h11|h12 = relu(x @ {fc11,fc12}^T + b)   [4096 x 2048]
    gemm_tf32<0><<<dim3(2 * E_ / BN, B_ / BM), THREADS, smemG>>>(
        x, D_, fc11_w, fc12_w, fc11_b, fc12_b, nullptr,
        hbuf, 2 * E_, B_, 2 * E_, D_, E_, 0);

    // 2) mu / logvar heads  [4096 x 68], z-batched
    gemm_tf32<1><<<dim3(1, B_ / BM, 2), THREADS, smemG>>>(
        hbuf, 2 * E_, fc21_w, fc22_w, fc21_b, fc22_b, nullptr,
        mu, L_, B_, L_, E_, E_, B_ * L_);

    // 3) reparam + y + decoder branch 0 -> h51
    mid_kernel<<<B_ / 8, 256, smemMid>>>(
        mu, lv, eps, W3, b3, W4, b4, W5, b5, fcy_w, fcy_b, h51, y);

    // 4) recon = sigmoid(outer(h51) @ fc6_w^T + b)  [4096 x 4624]
    gemm_tf32<2><<<dim3((D_ + BN - 1) / BN, B_ / BM), THREADS, smemG2>>>(
        nullptr, 0, fc6_w, nullptr, fc6_b, nullptr, h51,
        recon, D_, B_, D_, D_, 0, 0);
}

// round 2
// speedup vs baseline: 1.2971x; 1.2971x over previous
#include <cuda_runtime.h>
#include <cstdint>

// Problem dims
#define B_  4096
#define D_  4624
#define L_  68
#define E_  1024

// GEMM tiling
#define BM 128
#define BN 128
#define BK 32
#define KPAD 36          // smem row stride (u32): 16B-aligned, conflict-free frag loads
#define THREADS 256

// ---- static scratch (no cudaMalloc allowed) ----
__device__ float g_h  [(size_t)B_ * 2 * E_];   // relu(x@fc11^T)|relu(x@fc12^T), tf32-rounded
__device__ float g_h51[(size_t)B_ * L_];       // decoder branch-0 output
__device__ float g_x32[(size_t)B_ * D_];       // x, tf32-rounded
__device__ float g_w6 [(size_t)D_ * D_];       // fc6_w, tf32-rounded
__device__ float g_w1 [(size_t)2 * E_ * D_];   // fc11_w|fc12_w concat, tf32-rounded
__device__ float g_w2 [(size_t)2 * L_ * E_];   // fc21_w|fc22_w concat, tf32-rounded
__device__ float g_b1 [2 * E_];                // fc11_b|fc12_b concat (exact copy)

__device__ __forceinline__ uint32_t f2tf32(float x) {
    uint32_t r;
    asm("cvt.rna.tf32.f32 %0, %1;" : "=r"(r) : "f"(x));
    return r;
}

__device__ __forceinline__ void mma_tf32(float* c, uint32_t a0, uint32_t a1,
                                         uint32_t a2, uint32_t a3,
                                         uint32_t b0, uint32_t b1) {
    asm volatile(
        "mma.sync.aligned.m16n8k8.row.col.f32.tf32.tf32.f32 "
        "{%0,%1,%2,%3}, {%4,%5,%6,%7}, {%8,%9}, {%0,%1,%2,%3};\n"
        : "+f"(c[0]), "+f"(c[1]), "+f"(c[2]), "+f"(c[3])
        : "r"(a0), "r"(a1), "r"(a2), "r"(a3), "r"(b0), "r"(b1));
}

__device__ __forceinline__ void cp_async16(void* sptr, const void* gptr, int src_size) {
    uint32_t s = (uint32_t)__cvta_generic_to_shared(sptr);
    asm volatile("cp.async.cg.shared.global [%0], [%1], 16, %2;\n"
                 :: "r"(s), "l"(gptr), "r"(src_size));
}
__device__ __forceinline__ void cp_commit() {
    asm volatile("cp.async.commit_group;\n");
}
template <int N>
__device__ __forceinline__ void cp_wait() {
    asm volatile("cp.async.wait_group %0;\n" :: "n"(N));
}

// elementwise tf32 rounding (vectorized) — pre-pass so GEMMs can cp.async raw bits
__global__ void round_tf32_v4(const float4* __restrict__ in, float4* __restrict__ out, int n4) {
    int i = blockIdx.x * blockDim.x + threadIdx.x;
    int stride = gridDim.x * blockDim.x;
    for (; i < n4; i += stride) {
        float4 v = in[i];
        v.x = __uint_as_float(f2tf32(v.x));
        v.y = __uint_as_float(f2tf32(v.y));
        v.z = __uint_as_float(f2tf32(v.z));
        v.w = __uint_as_float(f2tf32(v.w));
        out[i] = v;
    }
}

// MODE 0: hbuf = round_tf32(relu(A @ W^T + b))    (encoder, concat fc11|fc12)
// MODE 1: C = A @ W^T + b, batched over blockIdx.z (mu / logvar heads)
// MODE 2: C = sigmoid(outer(h51) @ W^T + b); A synthesized from h51 (recon)
template <int MODE>
__global__ void __launch_bounds__(THREADS, 2)
gemm_cp(const float* __restrict__ A, int lda,
        const float* __restrict__ W,
        const float* __restrict__ bias0, const float* __restrict__ bias1,
        const float* __restrict__ h51,
        float* __restrict__ C, int ldc,
        int M, int N, int K, int Nw, int batchStrideC)
{
    extern __shared__ unsigned char smem_raw[];
    uint32_t* As   = reinterpret_cast<uint32_t*>(smem_raw);          // 2*BM*KPAD
    uint32_t* Bs   = As + 2 * BM * KPAD;                             // 2*BN*KPAD
    float*    h51s = reinterpret_cast<float*>(Bs + 2 * BN * KPAD);   // BM*68 (MODE 2)

    const int tid = threadIdx.x;
    const int m0  = blockIdx.y * BM;
    const int n0  = blockIdx.x * BN;

    const float* bias = bias0;
    if (MODE == 1) {
        int z = blockIdx.z;
        A   += (size_t)z * E_;          // column offset into g_h
        W   += (size_t)z * L_ * E_;
        bias = z ? bias1 : bias0;
        C   += (size_t)z * batchStrideC;
    }

    if (MODE == 2) {
        for (int idx = tid; idx < BM * L_; idx += THREADS)
            h51s[idx] = h51[(size_t)m0 * L_ + idx];
        __syncthreads();
    }

    const int lrow = tid >> 3;          // 0..31
    const int lcol = (tid & 7) * 4;     // 0,4,...,28 (floats)

    auto prefetch = [&](int t) {
        const int buf = t & 1;
        const int k0  = t * BK;
        uint32_t* Ab = As + buf * BM * KPAD;
        uint32_t* Bb = Bs + buf * BN * KPAD;
#pragma unroll
        for (int i = 0; i < 4; i++) {
            const int r = lrow + 32 * i;
            // ---- A ----
            if (MODE == 2) {
                const float* hr = h51s + r * L_;
                uint32_t v[4];
#pragma unroll
                for (int e = 0; e < 4; e++) {
                    int k = k0 + lcol + e;
                    float val = 0.f;
                    if (k < K) {
                        int ii = k / L_;
                        int jj = k - ii * L_;
                        val = hr[ii] * hr[jj];
                    }
                    v[e] = f2tf32(val);
                }
                *reinterpret_cast<uint4*>(Ab + r * KPAD + lcol) =
                    make_uint4(v[0], v[1], v[2], v[3]);
            } else {
                int srcsz = (k0 + lcol < K) ? 16 : 0;
                cp_async16(Ab + r * KPAD + lcol,
                           A + (size_t)(m0 + r) * lda + k0 + lcol, srcsz);
            }
            // ---- B (weights [Nw, K] row-major; NT gemm) ----
            {
                int row = n0 + r;
                int rr = row < Nw ? row : 0;                 // clamp addr
                int srcsz = (row < Nw && k0 + lcol < K) ? 16 : 0;
                cp_async16(Bb + r * KPAD + lcol,
                           W + (size_t)rr * K + k0 + lcol, srcsz);
            }
        }
        cp_commit();
    };

    float acc[2][8][4] = {};

    const int lane = tid & 31;
    const int warp = tid >> 5;
    const int wm = warp & 3;          // 4 warps along M
    const int wn = warp >> 2;         // 2 warps along N
    const int aBase = wm * 32 + (lane >> 2);
    const int bBase = wn * 64 + (lane >> 2);
    const int kq = lane & 3;

    auto compute = [&](int buf) {
        const uint32_t* Ab = As + buf * BM * KPAD;
        const uint32_t* Bb = Bs + buf * BN * KPAD;
#pragma unroll
        for (int kk = 0; kk < 4; kk++) {
            int k = kk * 8 + kq;
            uint32_t a[2][4];
#pragma unroll
            for (int mt = 0; mt < 2; mt++) {
                int r = aBase + mt * 16;
                a[mt][0] = Ab[r * KPAD + k];
                a[mt][1] = Ab[(r + 8) * KPAD + k];
                a[mt][2] = Ab[r * KPAD + k + 4];
                a[mt][3] = Ab[(r + 8) * KPAD + k + 4];
            }
#pragma unroll
            for (int nt = 0; nt < 8; nt++) {
                int c = bBase + nt * 8;
                uint32_t b0 = Bb[c * KPAD + k];
                uint32_t b1 = Bb[c * KPAD + k + 4];
#pragma unroll
                for (int mt = 0; mt < 2; mt++)
                    mma_tf32(acc[mt][nt], a[mt][0], a[mt][1], a[mt][2], a[mt][3],
                             b0, b1);
            }
        }
    };

    const int kt = (K + BK - 1) / BK;
    prefetch(0);
    for (int t = 0; t < kt; t++) {
        if (t + 1 < kt) {
            prefetch(t + 1);
            cp_wait<1>();
        } else {
            cp_wait<0>();
        }
        __syncthreads();
        compute(t & 1);
        __syncthreads();
    }

    // Epilogue: bias + activation + guarded store
#pragma unroll
    for (int mt = 0; mt < 2; mt++) {
        int row = m0 + wm * 32 + mt * 16 + (lane >> 2);
#pragma unroll
        for (int nt = 0; nt < 8; nt++) {
            int ncl = wn * 64 + nt * 8 + (lane & 3) * 2;
#pragma unroll
            for (int e = 0; e < 4; e++) {
                int r   = row + ((e >= 2) ? 8 : 0);
                int col = n0 + ncl + (e & 1);
                if (col < N) {
                    float v = acc[mt][nt][e] + bias[col];
                    if (MODE == 0) {
                        v = v > 0.f ? v : 0.f;
                        v = __uint_as_float(f2tf32(v));  // pre-round for next GEMM
                    }
                    if (MODE == 2) v = 1.0f / (1.0f + __expf(-v));
                    C[(size_t)r * ldc + col] = v;
                }
            }
        }
    }
}

// z = mu + eps*exp(0.5*logvar); y = mu@fcy^T+b;
// h3_0 = z@W3[0]^T+b3[0] (no sigmoid on branch 0);
// h4_0 = sigmoid(h3_0@W4[0]^T+b4[0]); h51 = h4_0@W5[0]^T+b5[0].
// Branches 1..4 are dead code w.r.t. the outputs — skipped.
__global__ void __launch_bounds__(256, 1)
mid_kernel(const float* __restrict__ mu, const float* __restrict__ logvar,
           const float* __restrict__ eps,
           const float* __restrict__ W3, const float* __restrict__ b3,
           const float* __restrict__ W4, const float* __restrict__ b4,
           const float* __restrict__ W5, const float* __restrict__ b5,
           const float* __restrict__ fcy_w, const float* __restrict__ fcy_b,
           float* __restrict__ h51, float* __restrict__ y)
{
    extern __shared__ unsigned char smem_raw[];
    float* s   = reinterpret_cast<float*>(smem_raw);
    float* sW3 = s;                    // 68*69 (padded: conflict-free)
    float* sW4 = sW3 + L_ * 69;
    float* sW5 = sW4 + L_ * 69;
    float* sb3 = sW5 + L_ * 69;
    float* sb4 = sb3 + L_;
    float* sb5 = sb4 + L_;
    float* zs  = sb5 + L_;             // 8*68
    float* h3s = zs + 8 * L_;
    float* h4s = h3s + 8 * L_;

    const int tid = threadIdx.x;
    for (int idx = tid; idx < L_ * L_; idx += 256) {
        int o = idx / L_, d = idx - o * L_;
        sW3[o * 69 + d] = W3[idx];     // branch 0 = first 68*68
        sW4[o * 69 + d] = W4[idx];
        sW5[o * 69 + d] = W5[idx];     // idx map [0,...] -> W5[0]
    }
    for (int idx = tid; idx < L_; idx += 256) {
        sb3[idx] = b3[idx]; sb4[idx] = b4[idx]; sb5[idx] = b5[idx];
    }
    __syncthreads();

    const int lane = tid & 31, w = tid >> 5;
    const int row = blockIdx.x * 8 + w;
    const float* murow  = mu + (size_t)row * L_;
    const float* lvrow  = logvar + (size_t)row * L_;
    const float* epsrow = eps + (size_t)row * L_;
    float* zw  = zs + w * L_;
    float* h3w = h3s + w * L_;
    float* h4w = h4s + w * L_;

    float yp = 0.f;
    for (int o = lane; o < L_; o += 32) {
        float m_ = murow[o];
        zw[o] = m_ + epsrow[o] * expf(0.5f * lvrow[o]);
        yp += m_ * fcy_w[o];
    }
#pragma unroll
    for (int off = 16; off; off >>= 1) yp += __shfl_xor_sync(0xffffffffu, yp, off);
    if (lane == 0) y[row] = yp + fcy_b[0];
    __syncwarp();

    for (int o = lane; o < L_; o += 32) {
        float sacc = sb3[o];
        const float* wr = sW3 + o * 69;
#pragma unroll 4
        for (int d = 0; d < L_; d++) sacc += zw[d] * wr[d];
        h3w[o] = sacc;                 // branch 0: NO sigmoid
    }
    __syncwarp();
    for (int o = lane; o < L_; o += 32) {
        float sacc = sb4[o];
        const float* wr = sW4 + o * 69;
#pragma unroll 4
        for (int d = 0; d < L_; d++) sacc += h3w[d] * wr[d];
        h4w[o] = 1.0f / (1.0f + expf(-sacc));
    }
    __syncwarp();
    for (int o = lane; o < L_; o += 32) {
        float sacc = sb5[o];
        const float* wr = sW5 + o * 69;
#pragma unroll 4
        for (int d = 0; d < L_; d++) sacc += h4w[d] * wr[d];
        h51[(size_t)row * L_ + o] = sacc;
    }
}

extern "C" void kernel_launch(void* const* d_in, const int* in_sizes, int n_in,
                              void* d_out, int out_size)
{
    const float* x      = (const float*)d_in[0];
    const float* eps    = (const float*)d_in[1];
    const float* fc11_w = (const float*)d_in[2];
    const float* fc11_b = (const float*)d_in[3];
    const float* fc12_w = (const float*)d_in[4];
    const float* fc12_b = (const float*)d_in[5];
    const float* fc21_w = (const float*)d_in[6];
    const float* fc21_b = (const float*)d_in[7];
    const float* fc22_w = (const float*)d_in[8];
    const float* fc22_b = (const float*)d_in[9];
    const float* W3     = (const float*)d_in[10];
    const float* b3     = (const float*)d_in[11];
    const float* W4     = (const float*)d_in[12];
    const float* b4     = (const float*)d_in[13];
    const float* W5     = (const float*)d_in[14];
    const float* b5     = (const float*)d_in[15];
    const float* fc6_w  = (const float*)d_in[16];
    const float* fc6_b  = (const float*)d_in[17];
    const float* fcy_w  = (const float*)d_in[18];
    const float* fcy_b  = (const float*)d_in[19];

    float* out   = (float*)d_out;
    float* recon = out;                                  // [B, D]
    float* mu    = out + (size_t)B_ * D_;                // [B, L]
    float* lv    = mu + (size_t)B_ * L_;                 // [B, L]
    float* y     = lv + (size_t)B_ * L_;                 // [B, 1]

    float* hbuf; cudaGetSymbolAddress((void**)&hbuf, g_h);
    float* h51;  cudaGetSymbolAddress((void**)&h51, g_h51);
    float* x32;  cudaGetSymbolAddress((void**)&x32, g_x32);
    float* w6;   cudaGetSymbolAddress((void**)&w6,  g_w6);
    float* w1;   cudaGetSymbolAddress((void**)&w1,  g_w1);
    float* w2;   cudaGetSymbolAddress((void**)&w2,  g_w2);
    float* b1;   cudaGetSymbolAddress((void**)&b1,  g_b1);

    // ---- pre-pass: tf32-round GEMM operands into scratch (~50us, HBM-bound) ----
    const int CT = 256, CB = 1024;
    round_tf32_v4<<<CB, CT>>>((const float4*)x,      (float4*)x32, (B_ * D_) / 4);
    round_tf32_v4<<<CB, CT>>>((const float4*)fc11_w, (float4*)w1,              (E_ * D_) / 4);
    round_tf32_v4<<<CB, CT>>>((const float4*)fc12_w, (float4*)(w1 + (size_t)E_ * D_), (E_ * D_) / 4);
    round_tf32_v4<<<CB, CT>>>((const float4*)fc21_w, (float4*)w2,              (L_ * E_) / 4);
    round_tf32_v4<<<CB, CT>>>((const float4*)fc22_w, (float4*)(w2 + (size_t)L_ * E_), (L_ * E_) / 4);
    round_tf32_v4<<<CB, CT>>>((const float4*)fc6_w,  (float4*)w6, (D_ * D_) / 4);
    cudaMemcpyAsync(b1,      fc11_b, E_ * sizeof(float), cudaMemcpyDeviceToDevice);
    cudaMemcpyAsync(b1 + E_, fc12_b, E_ * sizeof(float), cudaMemcpyDeviceToDevice);

    const size_t smemG   = (size_t)(2 * BM * KPAD + 2 * BN * KPAD) * 4;   // 73728
    const size_t smemG2  = smemG + (size_t)BM * L_ * 4;                   // 108544
    const size_t smemMid = (size_t)(3 * L_ * 69 + 3 * L_ + 3 * 8 * L_) * 4;

    cudaFuncSetAttribute(gemm_cp<0>, cudaFuncAttributeMaxDynamicSharedMemorySize, (int)smemG);
    cudaFuncSetAttribute(gemm_cp<1>, cudaFuncAttributeMaxDynamicSharedMemorySize, (int)smemG);
    cudaFuncSetAttribute(gemm_cp<2>, cudaFuncAttributeMaxDynamicSharedMemorySize, (int)smemG2);
    cudaFuncSetAttribute(mid_kernel, cudaFuncAttributeMaxDynamicSharedMemorySize, (int)smemMid);

    // 1) hbuf = round(relu(x @ [fc11|fc12]^T + b))   [4096 x 2048]
    gemm_cp<0><<<dim3(2 * E_ / BN, B_ / BM), THREADS, smemG>>>(
        x32, D_, w1, b1, nullptr, nullptr,
        hbuf, 2 * E_, B_, 2 * E_, D_, 2 * E_, 0);

    // 2) mu / logvar heads  [4096 x 68], z-batched
    gemm_cp<1><<<dim3(1, B_ / BM, 2), THREADS, smemG>>>(
        hbuf, 2 * E_, w2, fc21_b, fc22_b, nullptr,
        mu, L_, B_, L_, E_, L_, B_ * L_);

    // 3) reparam + y + decoder branch 0 -> h51
    mid_kernel<<<B_ / 8, 256, smemMid>>>(
        mu, lv, eps, W3, b3, W4, b4, W5, b5, fcy_w, fcy_b, h51, y);

    // 4) recon = sigmoid(outer(h51) @ fc6_w^T + b)  [4096 x 4624]
    gemm_cp<2><<<dim3((D_ + BN - 1) / BN, B_ / BM), THREADS, smemG2>>>(
        nullptr, 0, w6, fc6_b, nullptr, h51,
        recon, D_, B_, D_, D_, D_, 0);
}